// round 6
// baseline (speedup 1.0000x reference)
#include <cuda_runtime.h>
#include <cstdint>

#define NB 4
#define NS 2048
#define ND 1024
#define NE 8
#define NN 16
#define NR 4
#define JM 76   // M rows: 8 Wg | 64 A(r,n) | 4 const_w
#define JV 66   // V rows: 64 nk(r,n) | 2 const_c

// ---------------- scratch (device globals; no allocs allowed) ----------------
__device__ __align__(16) float g_M[NB][JM][ND];
__device__ __align__(16) float g_V[NB][JV][ND];
__device__ float g_sA[NB][64];
__device__ float g_bc[NB][64];
__device__ float g_Yt[NB][JM][NS];      // transposed: Y[j][s], raw dot(x, M)
__device__ float g_statsT[NB][2][NS];   // [0]=sum(x), [1]=sum(x^2)
__device__ float g_cT[NB][68][NS];      // [0..63]=c(r,n), [64..65]=gamma, [66]=2*alpha

typedef unsigned long long ull;

__device__ __forceinline__ void ffma2(ull &acc, ull a, ull b){
    asm("fma.rn.f32x2 %0, %1, %2, %0;" : "+l"(acc) : "l"(a), "l"(b));
}
__device__ __forceinline__ ull packf2(float f){
    ull r; asm("mov.b64 %0, {%1, %1};" : "=l"(r) : "f"(f)); return r;
}
__device__ __forceinline__ float2 unpackf2(ull v){
    float2 r; asm("mov.b64 {%0, %1}, %2;" : "=f"(r.x), "=f"(r.y) : "l"(v)); return r;
}

// ---------------- K0a: LN(ref) -> nk rows of V, A rows of M, sA, bconst -----
__global__ __launch_bounds__(256) void k0a(const float* __restrict__ ref,
        const float* __restrict__ lnq_s, const float* __restrict__ lnq_b,
        const float* __restrict__ lnk_s, const float* __restrict__ lnk_b){
    int b = blockIdx.x >> 4, n = blockIdx.x & 15;
    int tid = threadIdx.x;
    __shared__ float nr_s[ND];
    __shared__ float rb1[8], rb2[8];
    const float4 v = reinterpret_cast<const float4*>(ref + (size_t)(b*NN+n)*ND)[tid];
    float s = v.x+v.y+v.z+v.w;
    float q = v.x*v.x+v.y*v.y+v.z*v.z+v.w*v.w;
    #pragma unroll
    for(int o=16;o;o>>=1){ s += __shfl_xor_sync(0xffffffffu,s,o); q += __shfl_xor_sync(0xffffffffu,q,o); }
    if((tid&31)==0){ rb1[tid>>5]=s; rb2[tid>>5]=q; }
    __syncthreads();
    float S1=0.f,Q1=0.f;
    #pragma unroll
    for(int i=0;i<8;i++){ S1+=rb1[i]; Q1+=rb2[i]; }
    float mu = S1*(1.f/ND);
    float var = Q1*(1.f/ND) - mu*mu;
    float rs = rsqrtf(var + 1e-5f);
    float4 nr4;
    nr4.x=(v.x-mu)*rs; nr4.y=(v.y-mu)*rs; nr4.z=(v.z-mu)*rs; nr4.w=(v.w-mu)*rs;
    reinterpret_cast<float4*>(nr_s)[tid] = nr4;
    __syncthreads();
    for(int r=0;r<NR;r++){
        float psA=0.f, pbc=0.f;
        for(int d=tid; d<ND; d+=256){
            float nk = nr_s[d]*lnk_s[r*ND+d] + lnk_b[r*ND+d];
            g_V[b][r*NN+n][d] = nk;
            float a = lnq_s[r*ND+d]*nk;
            g_M[b][8 + r*NN + n][d] = a;
            psA += a;
            pbc += lnq_b[r*ND+d]*nk;
        }
        #pragma unroll
        for(int o=16;o;o>>=1){ psA += __shfl_xor_sync(0xffffffffu,psA,o); pbc += __shfl_xor_sync(0xffffffffu,pbc,o); }
        __syncthreads();
        if((tid&31)==0){ rb1[tid>>5]=psA; rb2[tid>>5]=pbc; }
        __syncthreads();
        if(tid==0){
            float A1=0.f,B1=0.f;
            #pragma unroll
            for(int i=0;i<8;i++){ A1+=rb1[i]; B1+=rb2[i]; }
            g_sA[b][r*NN+n]=A1; g_bc[b][r*NN+n]=B1;
        }
    }
}

// ---------------- K0b: copy Wg / const_w rows into M, const_c into V --------
__global__ void k0b(const float* __restrict__ Wg, const float* __restrict__ cw,
                    const float* __restrict__ cc){
    int i = blockIdx.x*blockDim.x + threadIdx.x;
    const int S1 = NB*NE*ND;          // 32768
    const int S2 = S1 + NB*4*ND;      // 49152
    const int S3 = S2 + NB*2*ND;      // 57344
    if(i < S1){
        int b = i >> 13; int rem = i & (NE*ND-1);
        g_M[b][rem>>10][rem&1023] = Wg[rem];
    } else if(i < S2){
        int j = i - S1;
        int b = j >> 12; int rem = j & (4*ND-1);
        g_M[b][72+(rem>>10)][rem&1023] = cw[rem];
    } else if(i < S3){
        int j = i - S2;
        int b = j >> 11; int rem = j & (2*ND-1);
        g_V[b][64+(rem>>10)][rem&1023] = cc[rem];
    }
}

// ---------------- K1: Y = x @ M^T + per-token stats --------------------------
// 256 blocks x 256 threads; 32 tokens/block, 4 tokens/warp, x rows in regs.
// M staged through double-buffered smem (1 sync/group); each block reads M once.
__global__ __launch_bounds__(256) void k1(const float* __restrict__ x){
    int b  = blockIdx.x >> 6;
    int s0 = (blockIdx.x & 63) << 5;
    int warp = threadIdx.x >> 5, lane = threadIdx.x & 31;
    int tid = threadIdx.x;
    int t0 = s0 + warp*4;
    __shared__ ulonglong2 ms[2][1024];   // 2 x (4 M rows = 16KB)
    __shared__ float ys[JM][32];         // Y staging for coalesced writes
    // x: 4 tokens x 8 ulonglong2 (each thread covers 32 d-floats per token)
    ulonglong2 xa[4][8];
    #pragma unroll
    for(int t=0;t<4;t++){
        const ulonglong2* xp = reinterpret_cast<const ulonglong2*>(x) + (size_t)(b*NS + t0 + t)*(ND/4);
        #pragma unroll
        for(int k=0;k<8;k++) xa[t][k] = xp[lane + 32*k];
    }
    // stats (raw x; scaled to xs in K2)
    #pragma unroll
    for(int t=0;t<4;t++){
        float sa=0.f,qa=0.f;
        #pragma unroll
        for(int k=0;k<8;k++){
            float2 p0=unpackf2(xa[t][k].x), p1=unpackf2(xa[t][k].y);
            sa += (p0.x+p0.y)+(p1.x+p1.y);
            qa += (p0.x*p0.x+p0.y*p0.y)+(p1.x*p1.x+p1.y*p1.y);
        }
        #pragma unroll
        for(int o=16;o;o>>=1){
            sa += __shfl_xor_sync(0xffffffffu,sa,o); qa += __shfl_xor_sync(0xffffffffu,qa,o);
        }
        if(lane==0){ g_statsT[b][0][t0+t]=sa; g_statsT[b][1][t0+t]=qa; }
    }
    const ulonglong2* Mbase = reinterpret_cast<const ulonglong2*>(g_M[b][0]);
    ulonglong2 pre[4];
    #pragma unroll
    for(int i=0;i<4;i++) pre[i] = Mbase[i*256 + tid];
    #pragma unroll
    for(int i=0;i<4;i++) ms[0][i*256 + tid] = pre[i];
    for(int g=0; g<JM/4; g++){
        if(g+1 < JM/4){
            #pragma unroll
            for(int i=0;i<4;i++) pre[i] = Mbase[(size_t)(g+1)*1024 + i*256 + tid];
        }
        __syncthreads();
        const ulonglong2* msb = ms[g&1];
        #pragma unroll
        for(int jj=0;jj<4;jj++){
            const ulonglong2* Mp = msb + jj*256;
            ull acc[4][2];
            #pragma unroll
            for(int t=0;t<4;t++){ acc[t][0]=0ull; acc[t][1]=0ull; }
            #pragma unroll
            for(int k=0;k<8;k++){
                ulonglong2 m = Mp[lane + 32*k];
                #pragma unroll
                for(int t=0;t<4;t++){
                    ffma2(acc[t][0], xa[t][k].x, m.x);
                    ffma2(acc[t][1], xa[t][k].y, m.y);
                }
            }
            #pragma unroll
            for(int t=0;t<4;t++){
                float2 f0=unpackf2(acc[t][0]), f1=unpackf2(acc[t][1]);
                float r = (f0.x+f0.y)+(f1.x+f1.y);
                #pragma unroll
                for(int o=16;o;o>>=1) r += __shfl_xor_sync(0xffffffffu,r,o);
                if(lane==0) ys[g*4+jj][warp*4+t] = r;
            }
        }
        if(g+1 < JM/4){
            #pragma unroll
            for(int i=0;i<4;i++) ms[(g+1)&1][i*256 + tid] = pre[i];
        }
    }
    __syncthreads();
    for(int i=tid; i<JM*32; i+=256){
        int j = i>>5, tt = i&31;
        g_Yt[b][j][s0+tt] = ys[j][tt];
    }
}

// ---------------- K2: per-token gating/softmax -> coefficients + logits -----
// 256 blocks x 32 threads: full-chip spread (fix grid=32 underutilization).
__global__ __launch_bounds__(32) void k2(const float* __restrict__ Wmap, float* __restrict__ logits_out){
    int t = blockIdx.x*32 + threadIdx.x;
    int b = t >> 11, s = t & (NS-1);
    int tid = threadIdx.x;
    __shared__ float wm[64], sA_s[64], bc_s[64];
    wm[tid]      = Wmap[tid];
    wm[tid+32]   = Wmap[tid+32];
    sA_s[tid]    = g_sA[b][tid];
    sA_s[tid+32] = g_sA[b][tid+32];
    bc_s[tid]    = g_bc[b][tid];
    bc_s[tid+32] = g_bc[b][tid+32];
    __syncwarp();
    // logits = L0 + Wmap @ L0_prev
    float l[NE], yp[NE];
    #pragma unroll
    for(int e=0;e<NE;e++) l[e] = g_Yt[b][e][s];
    #pragma unroll
    for(int e=0;e<NE;e++) yp[e] = (s>0)? g_Yt[b][e][s-1] : 0.f;
    #pragma unroll
    for(int f=0;f<NE;f++){
        float acc = l[f];
        #pragma unroll
        for(int e=0;e<NE;e++) acc += wm[f*8+e]*yp[e];
        l[f] = acc;
    }
    if(logits_out){
        float4* lp = reinterpret_cast<float4*>(logits_out + (size_t)t*8);
        float4 a; a.x=l[0]; a.y=l[1]; a.z=l[2]; a.w=l[3];
        float4 c; c.x=l[4]; c.y=l[5]; c.z=l[6]; c.w=l[7];
        lp[0]=a; lp[1]=c;
    }
    // softmax over E, top-2, zero expert 7, renormalize
    float mx = l[0];
    #pragma unroll
    for(int e=1;e<NE;e++) mx = fmaxf(mx, l[e]);
    float ge[NE]; float gs = 0.f;
    #pragma unroll
    for(int e=0;e<NE;e++){ ge[e] = expf(l[e]-mx); gs += ge[e]; }
    int i1 = 0;
    #pragma unroll
    for(int e=1;e<NE;e++) if(ge[e] > ge[i1]) i1 = e;
    int i2 = (i1==0) ? 1 : 0;
    #pragma unroll
    for(int e=0;e<NE;e++) if(e!=i1 && ge[e] > ge[i2]) i2 = e;
    float tg1 = (i1==NE-1) ? 0.f : ge[i1]/gs;
    float tg2 = (i2==NE-1) ? 0.f : ge[i2]/gs;
    float inv_ts = 1.f/(tg1+tg2);
    tg1 *= inv_ts; tg2 *= inv_ts;
    float w[NE];
    #pragma unroll
    for(int e=0;e<NE;e++) w[e] = (e==i1 ? tg1 : 0.f) + (e==i2 ? tg2 : 0.f);
    // LN stats of xs = 2x
    float mu  = 2.f*g_statsT[b][0][s]*(1.f/ND);
    float msq = 4.f*g_statsT[b][1][s]*(1.f/ND);
    float var = msq - mu*mu;
    float rs  = rsqrtf(var + 1e-5f);
    float alpha = w[0]+w[1]+w[2]+w[3]+w[6];
    // attention coefficients per r (always compute; wr==0 -> zeros, no divergence)
    for(int r=0;r<NR;r++){
        float wr = w[r];
        float sc[NN]; float smx = -1e30f;
        #pragma unroll
        for(int n=0;n<NN;n++){
            float ya = g_Yt[b][8+r*NN+n][s];
            float v = rs*(2.f*ya - mu*sA_s[r*NN+n]) + bc_s[r*NN+n];
            sc[n] = v; smx = fmaxf(smx, v);
        }
        float es = 0.f;
        #pragma unroll
        for(int n=0;n<NN;n++){ sc[n] = expf(sc[n]-smx); es += sc[n]; }
        float invw = wr/es;
        #pragma unroll
        for(int n=0;n<NN;n++) g_cT[b][r*NN+n][s] = sc[n]*invw;
    }
    // const heads (softmax over 2)
    #pragma unroll
    for(int c=0;c<2;c++){
        float a  = 2.f*g_Yt[b][72+2*c][s];
        float bb = 2.f*g_Yt[b][73+2*c][s];
        float mm = fmaxf(a,bb);
        float ea = expf(a-mm), eb = expf(bb-mm);
        float inv = 1.f/(ea+eb);
        float wcc = w[4+c];
        alpha += wcc*ea*inv;
        g_cT[b][64+c][s] = wcc*eb*inv;
    }
    g_cT[b][66][s] = 2.f*alpha;   // applied to raw x in K3
}

// ---------------- K3: out = (2*alpha)*x + coef @ V ---------------------------
__global__ __launch_bounds__(256) void k3(const float* __restrict__ x, float* __restrict__ out){
    int b  = blockIdx.x >> 7;
    int s0 = (blockIdx.x & 127) << 4;
    int tid = threadIdx.x;
    __shared__ ull csm[16][68];
    for(int i=tid; i<16*67; i+=256){
        int j = i>>4, tt = i&15;
        csm[tt][j] = packf2(g_cT[b][j][s0+tt]);
    }
    __syncthreads();
    ull acc[16][2];
    #pragma unroll
    for(int t=0;t<16;t++){
        ulonglong2 xv = (reinterpret_cast<const ulonglong2*>(x) + (size_t)(b*NS+s0+t)*(ND/4))[tid];
        ull a2 = csm[t][66];
        acc[t][0]=0ull; acc[t][1]=0ull;
        ffma2(acc[t][0], a2, xv.x);
        ffma2(acc[t][1], a2, xv.y);
    }
    const ulonglong2* Vb = reinterpret_cast<const ulonglong2*>(g_V[b][0]);
    // 2-deep register prefetch of V rows to hide L2 latency under ffma2 stream
    ulonglong2 vn0 = Vb[0*256 + tid];
    ulonglong2 vn1 = Vb[1*256 + tid];
    for(int j=0;j<JV;j++){
        ulonglong2 v = vn0;
        vn0 = vn1;
        if(j+2 < JV) vn1 = Vb[(size_t)(j+2)*256 + tid];
        #pragma unroll
        for(int t=0;t<16;t++){
            ull c2 = csm[t][j];
            ffma2(acc[t][0], c2, v.x);
            ffma2(acc[t][1], c2, v.y);
        }
    }
    #pragma unroll
    for(int t=0;t<16;t++){
        ulonglong2 o; o.x=acc[t][0]; o.y=acc[t][1];
        (reinterpret_cast<ulonglong2*>(out) + (size_t)(b*NS+s0+t)*(ND/4))[tid] = o;
    }
}

// ---------------- launch -----------------------------------------------------
extern "C" void kernel_launch(void* const* d_in, const int* in_sizes, int n_in,
                              void* d_out, int out_size) {
    (void)in_sizes; (void)n_in;
    const float* x     = (const float*)d_in[0];
    const float* Wg    = (const float*)d_in[1];
    const float* Wmap  = (const float*)d_in[2];
    const float* lnq_s = (const float*)d_in[3];
    const float* lnq_b = (const float*)d_in[4];
    const float* lnk_s = (const float*)d_in[5];
    const float* lnk_b = (const float*)d_in[6];
    const float* ref   = (const float*)d_in[7];
    const float* cc    = (const float*)d_in[8];
    const float* cw    = (const float*)d_in[9];
    float* out = (float*)d_out;
    const long long OUT_MAIN = (long long)NB*NS*ND;            // 8388608
    const long long OUT_FULL = OUT_MAIN + (long long)NB*NS*NE; // 8454144
    float* logits_out = (out_size >= OUT_FULL) ? out + OUT_MAIN : nullptr;

    k0a<<<NB*NN, 256>>>(ref, lnq_s, lnq_b, lnk_s, lnk_b);
    k0b<<<224, 256>>>(Wg, cw, cc);
    k1<<<256, 256>>>(x);
    k2<<<256, 32>>>(Wmap, logits_out);
    k3<<<512, 256>>>(x, out);
}